// round 3
// baseline (speedup 1.0000x reference)
#include <cuda_runtime.h>
#include <math.h>

#define BB   128
#define TT   256
#define SS   64
#define IIN  3
#define HH   512
#define KK   10
#define CSL  60
#define OUTD 121
#define G4   2048          // 4*H
#define K1TOT 575          // IN+CSL+H
#define K2TOT 512
#define NSPL 8
#define NBLK 128           // persistent grid size (all co-resident on 148 SMs)

// ---------------- scratch (static device allocations; no cudaMalloc) ----------
__device__ float g_h1[BB*HH];
__device__ float g_c1[BB*HH];
__device__ float g_h2[BB*HH];
__device__ float g_c2[BB*HH];
__device__ float g_h1T[HH*BB];          // [h][b]
__device__ float g_h2T[HH*BB];          // [h][b]
__device__ float g_p[BB*3*KK];
__device__ float g_winT[CSL*BB];        // [c][b] current window
__device__ float g_winsT[TT*CSL*BB];    // [t][c][b]
__device__ float g_hxT[(size_t)TT*HH*BB];       // [t][h][b]  layer-1 h outputs
__device__ float g_gp[(size_t)NSPL*BB*G4];      // split-K partials [s][b][j]
__device__ float g_l2in[(size_t)TT*BB*G4];      // layer-2 input gates [t][b][j]
__device__ float g_yT[(size_t)HH*TT*BB];        // [h][t*BB+b]  layer-2 outputs

// ---------------- software grid barrier (all NBLK blocks resident) ------------
__device__ unsigned g_cnt = 0;
__device__ volatile unsigned g_gen = 0;

__device__ __forceinline__ void gbar()
{
    __syncthreads();
    if (threadIdx.x == 0){
        unsigned my = g_gen;
        __threadfence();                       // release: flush my block's writes
        if (atomicAdd(&g_cnt, 1u) == NBLK-1u){
            g_cnt = 0;
            __threadfence();
            g_gen = my + 1u;                   // release all waiters
        } else {
            while (g_gen == my) __nanosleep(64);
        }
        __threadfence();                       // acquire: invalidate stale L1 (CCTL.IVALL)
    }
    __syncthreads();
}

__device__ __forceinline__ float sigf(float x){ return 1.0f/(1.0f+expf(-x)); }

// ---------------- init: load initial states, zero attention carry -------------
__global__ void k_init(const float* __restrict__ h1h, const float* __restrict__ h1c,
                       const float* __restrict__ h2h, const float* __restrict__ h2c)
{
    int i = blockIdx.x*blockDim.x + threadIdx.x;
    if (i < BB*HH){
        int b = i/HH, h = i%HH;
        float a=h1h[i], c=h1c[i], d=h2h[i], e=h2c[i];
        g_h1[i]=a; g_c1[i]=c; g_h2[i]=d; g_c2[i]=e;
        g_h1T[h*BB+b]=a; g_h2T[h*BB+b]=d;
    }
    if (i < BB*3*KK) g_p[i] = 0.f;
}

// ================= persistent layer-1: attention + LSTMCell recurrence ========
// 128 blocks x 256 threads. Per step:
//   phase A (block b): cell(t-1) consume split-K partials, then attention(t)
//   gbar
//   phase B: GEMM gates(t) partial = [x_t|win_t|h1_t] @ W^T, weights SMEM-resident
//   gbar
__global__ void __launch_bounds__(256,1)
k_rec1(const float* __restrict__ x,    const float* __restrict__ Wihc,
       const float* __restrict__ Whhc, const float* __restrict__ bc,
       const float* __restrict__ W1,   const float* __restrict__ b1,
       const float* __restrict__ sent)
{
    __shared__ float Wp[72*128];       // persistent weight tile (36.8 KB)
    __shared__ float As[8][128];
    __shared__ float sh[HH];
    __shared__ float sp[3*KK];
    __shared__ float sphi[SS];

    const int tid = threadIdx.x;
    const int blk = blockIdx.x;
    const int b   = blk;
    const int j0  = (blk & 15) * 128;
    const int spl = blk >> 4;
    const int k0  = spl * 72;
    const int kend = min(K1TOT, k0 + 72);
    const int mi = tid & 15, ni = tid >> 4;

    // preload weight tile once; zero-fill tail (so A=0 x W=0 in guard region)
    for (int i = tid; i < 72*128; i += 256){
        int kk = i >> 7, jl = i & 127;
        int kg = k0 + kk, j = j0 + jl;
        float v = 0.f;
        if (kg < kend)
            v = (kg < 63) ? Wihc[(size_t)j*63 + kg] : Whhc[(size_t)j*512 + (kg-63)];
        Wp[i] = v;
    }

    for (int t = 0; t < TT; t++){
        // -------- phase A: cell(t-1) + attention(t), block handles batch b ----
        if (t > 0){
            for (int h = tid; h < HH; h += 256){
                float gi=bc[h], gf=bc[HH+h], gg=bc[2*HH+h], go=bc[3*HH+h];
                #pragma unroll
                for (int s=0;s<NSPL;s++){
                    const float* gp = g_gp + (size_t)s*BB*G4 + (size_t)b*G4;
                    gi += gp[h]; gf += gp[HH+h]; gg += gp[2*HH+h]; go += gp[3*HH+h];
                }
                float c  = g_c1[b*HH+h];
                float cn = sigf(gf)*c + sigf(gi)*tanhf(gg);
                float hn = sigf(go)*tanhf(cn);
                g_c1[b*HH+h]=cn;
                g_h1T[h*BB+b]=hn;
                g_hxT[((size_t)(t-1)*HH + h)*BB + b] = hn;
                sh[h]=hn;
            }
        } else {
            for (int h = tid; h < HH; h += 256) sh[h] = g_h1[b*HH+h];
        }
        __syncthreads();

        // attention: ip = exp(h @ W1^T + b1); kappa subtracts previous kappa
        {
            int w = tid>>5, lane = tid&31;
            for (int j = w; j < 3*KK; j += 8){
                float s = 0.f;
                for (int k = lane; k < HH; k += 32) s += sh[k]*W1[j*HH+k];
                #pragma unroll
                for (int o=16;o;o>>=1) s += __shfl_down_sync(0xffffffffu, s, o);
                if (lane == 0){
                    float v = expf(s + b1[j]);
                    if (j >= 2*KK) v -= g_p[b*3*KK + j];
                    g_p[b*3*KK + j] = v;
                    sp[j] = v;
                }
            }
            __syncthreads();
            if (tid < SS){
                float u = (float)(tid+1);
                float acc = 0.f;
                #pragma unroll
                for (int k=0;k<KK;k++){
                    float d = sp[2*KK+k] - u;
                    acc += sp[k]*expf(-sp[KK+k]*d*d);
                }
                sphi[tid] = acc;
            }
            __syncthreads();
            if (tid < CSL){
                float acc = 0.f;
                #pragma unroll 8
                for (int s=0;s<SS;s++) acc += sphi[s]*sent[((size_t)b*SS+s)*CSL + tid];
                g_winT[tid*BB + b] = acc;
                g_winsT[((size_t)t*CSL + tid)*BB + b] = acc;
            }
        }
        gbar();

        // -------- phase B: recurrent GEMM, SMEM-resident weights --------------
        {
            float acc[8][8];
            #pragma unroll
            for (int i=0;i<8;i++)
                #pragma unroll
                for (int j=0;j<8;j++) acc[i][j] = 0.f;

            for (int kt = 0; kt < 72; kt += 8){
                __syncthreads();
                #pragma unroll
                for (int r=0;r<4;r++){
                    int ii = tid + 256*r;
                    int kk = ii >> 7, m = ii & 127;
                    int kg = k0 + kt + kk;
                    float v = 0.f;
                    if (kg < kend){
                        if      (kg < IIN)      v = x[((size_t)m*TT + t)*IIN + kg];
                        else if (kg < IIN+CSL)  v = g_winT[(kg-IIN)*BB + m];
                        else                    v = g_h1T[(kg-63)*BB + m];
                    }
                    As[kk][m] = v;
                }
                __syncthreads();
                #pragma unroll
                for (int kk=0;kk<8;kk++){
                    float a[8], wv[8];
                    #pragma unroll
                    for (int i=0;i<8;i++) a[i]  = As[kk][mi*8+i];
                    #pragma unroll
                    for (int j=0;j<8;j++) wv[j] = Wp[(kt+kk)*128 + ni*8+j];
                    #pragma unroll
                    for (int i=0;i<8;i++)
                        #pragma unroll
                        for (int j=0;j<8;j++) acc[i][j] += a[i]*wv[j];
                }
            }
            float* outp = g_gp + (size_t)spl*BB*G4;
            #pragma unroll
            for (int i=0;i<8;i++){
                int m = mi*8+i;
                float4* p = (float4*)(outp + (size_t)m*G4 + j0 + ni*8);
                p[0] = make_float4(acc[i][0],acc[i][1],acc[i][2],acc[i][3]);
                p[1] = make_float4(acc[i][4],acc[i][5],acc[i][6],acc[i][7]);
            }
        }
        gbar();
    }

    // final cell (t = TT-1 consumed) -> final h1/c1 states + hxT[TT-1]
    for (int h = tid; h < HH; h += 256){
        float gi=bc[h], gf=bc[HH+h], gg=bc[2*HH+h], go=bc[3*HH+h];
        #pragma unroll
        for (int s=0;s<NSPL;s++){
            const float* gp = g_gp + (size_t)s*BB*G4 + (size_t)b*G4;
            gi += gp[h]; gf += gp[HH+h]; gg += gp[2*HH+h]; go += gp[3*HH+h];
        }
        float c  = g_c1[b*HH+h];
        float cn = sigf(gf)*c + sigf(gi)*tanhf(gg);
        float hn = sigf(go)*tanhf(cn);
        g_c1[b*HH+h]=cn; g_h1[b*HH+h]=hn;
        g_hxT[((size_t)(TT-1)*HH + h)*BB + b] = hn;
    }
}

// ---------------- layer-2 input gates for ALL timesteps (big parallel GEMM) ---
__global__ void __launch_bounds__(256) k_l2in(const float* __restrict__ x,
        const float* __restrict__ Wih, const float* __restrict__ bl)
{
    __shared__ float As[8][128];
    __shared__ float Ws[8][132];
    int j0 = blockIdx.x*128;
    int t  = blockIdx.y;
    int tid = threadIdx.x;
    int mi = tid & 15, ni = tid >> 4;

    float acc[8][8];
    #pragma unroll
    for (int i=0;i<8;i++)
        #pragma unroll
        for (int j=0;j<8;j++) acc[i][j] = 0.f;

    for (int kt = 0; kt < K1TOT; kt += 8){
        __syncthreads();
        #pragma unroll
        for (int r=0;r<4;r++){
            int ii = tid + 256*r;
            int kk = ii >> 7, m = ii & 127;
            int kg = kt + kk;
            float v = 0.f;
            if (kg < K1TOT){
                if      (kg < IIN)     v = x[((size_t)m*TT + t)*IIN + kg];
                else if (kg < IIN+CSL) v = g_winsT[((size_t)t*CSL + (kg-IIN))*BB + m];
                else                   v = g_hxT[((size_t)t*HH + (kg-63))*BB + m];
            }
            As[kk][m] = v;
        }
        #pragma unroll
        for (int r=0;r<4;r++){
            int ii = tid + 256*r;
            int jl = ii >> 3, kk = ii & 7;
            int kg = kt + kk;
            float v = 0.f;
            if (kg < K1TOT) v = Wih[(size_t)(j0+jl)*K1TOT + kg];
            Ws[kk][jl] = v;
        }
        __syncthreads();
        #pragma unroll
        for (int kk=0;kk<8;kk++){
            float a[8], wv[8];
            #pragma unroll
            for (int i=0;i<8;i++) a[i]  = As[kk][mi*8+i];
            #pragma unroll
            for (int j=0;j<8;j++) wv[j] = Ws[kk][ni*8+j];
            #pragma unroll
            for (int i=0;i<8;i++)
                #pragma unroll
                for (int j=0;j<8;j++) acc[i][j] += a[i]*wv[j];
        }
    }
    float bb[8];
    #pragma unroll
    for (int j=0;j<8;j++) bb[j] = bl[j0 + ni*8 + j];
    #pragma unroll
    for (int i=0;i<8;i++){
        int m = mi*8+i;
        float4* p = (float4*)(g_l2in + ((size_t)t*BB + m)*G4 + j0 + ni*8);
        p[0] = make_float4(acc[i][0]+bb[0],acc[i][1]+bb[1],acc[i][2]+bb[2],acc[i][3]+bb[3]);
        p[1] = make_float4(acc[i][4]+bb[4],acc[i][5]+bb[5],acc[i][6]+bb[6],acc[i][7]+bb[7]);
    }
}

// ================= persistent layer-2 recurrence ==============================
// 128 blocks x 256 threads. Per step:
//   phase B: GEMM h2 @ W_hh_l^T (split-K partials), weights SMEM-resident
//   gbar
//   phase A (block b): cell2(t) = l2in(t) + partials
//   gbar
__global__ void __launch_bounds__(256,1)
k_rec2(const float* __restrict__ Whhl)
{
    __shared__ float Wp[64*128];   // 32 KB persistent weight tile
    __shared__ float As[8][128];

    const int tid = threadIdx.x;
    const int blk = blockIdx.x;
    const int b   = blk;
    const int j0  = (blk & 15) * 128;
    const int spl = blk >> 4;
    const int k0  = spl * 64;
    const int mi = tid & 15, ni = tid >> 4;

    for (int i = tid; i < 64*128; i += 256){
        int kk = i >> 7, jl = i & 127;
        Wp[i] = Whhl[(size_t)(j0+jl)*K2TOT + k0 + kk];
    }

    for (int t = 0; t < TT; t++){
        // -------- GEMM: partial = h2 @ W_hh_l^T ------------------------------
        {
            float acc[8][8];
            #pragma unroll
            for (int i=0;i<8;i++)
                #pragma unroll
                for (int j=0;j<8;j++) acc[i][j] = 0.f;

            for (int kt = 0; kt < 64; kt += 8){
                __syncthreads();
                #pragma unroll
                for (int r=0;r<4;r++){
                    int ii = tid + 256*r;
                    int kk = ii >> 7, m = ii & 127;
                    As[kk][m] = g_h2T[(k0 + kt + kk)*BB + m];
                }
                __syncthreads();
                #pragma unroll
                for (int kk=0;kk<8;kk++){
                    float a[8], wv[8];
                    #pragma unroll
                    for (int i=0;i<8;i++) a[i]  = As[kk][mi*8+i];
                    #pragma unroll
                    for (int j=0;j<8;j++) wv[j] = Wp[(kt+kk)*128 + ni*8+j];
                    #pragma unroll
                    for (int i=0;i<8;i++)
                        #pragma unroll
                        for (int j=0;j<8;j++) acc[i][j] += a[i]*wv[j];
                }
            }
            float* outp = g_gp + (size_t)spl*BB*G4;
            #pragma unroll
            for (int i=0;i<8;i++){
                int m = mi*8+i;
                float4* p = (float4*)(outp + (size_t)m*G4 + j0 + ni*8);
                p[0] = make_float4(acc[i][0],acc[i][1],acc[i][2],acc[i][3]);
                p[1] = make_float4(acc[i][4],acc[i][5],acc[i][6],acc[i][7]);
            }
        }
        gbar();

        // -------- cell2(t): block handles batch b, h = tid, tid+256 -----------
        {
            const float* li = g_l2in + ((size_t)t*BB + b)*G4;
            #pragma unroll
            for (int hh=0; hh<2; hh++){
                int h = tid + hh*256;
                float gi = li[h], gf = li[HH+h], gg = li[2*HH+h], go = li[3*HH+h];
                #pragma unroll
                for (int s=0;s<NSPL;s++){
                    const float* gp = g_gp + (size_t)s*BB*G4 + (size_t)b*G4;
                    gi += gp[h]; gf += gp[HH+h]; gg += gp[2*HH+h]; go += gp[3*HH+h];
                }
                float c  = g_c2[b*HH+h];
                float cn = sigf(gf)*c + sigf(gi)*tanhf(gg);
                float hn = sigf(go)*tanhf(cn);
                g_c2[b*HH+h]=cn;
                g_h2T[h*BB+b]=hn;
                g_yT[(size_t)h*(TT*BB) + t*BB + b] = hn;
                if (t == TT-1) g_h2[b*HH+h] = hn;
            }
        }
        gbar();
    }
}

// ---------------- output projection: out[b*T+t, :] = y @ W2^T + b2 ------------
__global__ void __launch_bounds__(256) k_out(const float* __restrict__ W2,
        const float* __restrict__ b2, float* __restrict__ out)
{
    __shared__ float As[8][128];
    __shared__ float Ws[8][132];
    int m0 = blockIdx.x*128;       // rows ordered r2 = t*BB + b
    int tid = threadIdx.x;
    int mi = tid & 15, ni = tid >> 4;

    float acc[8][8];
    #pragma unroll
    for (int i=0;i<8;i++)
        #pragma unroll
        for (int j=0;j<8;j++) acc[i][j] = 0.f;

    for (int kt = 0; kt < K2TOT; kt += 8){
        __syncthreads();
        #pragma unroll
        for (int r=0;r<4;r++){
            int ii = tid + 256*r;
            int kk = ii >> 7, m = ii & 127;
            As[kk][m] = g_yT[(size_t)(kt+kk)*(TT*BB) + m0 + m];
        }
        #pragma unroll
        for (int r=0;r<4;r++){
            int ii = tid + 256*r;
            int jl = ii >> 3, kk = ii & 7;
            float v = 0.f;
            if (jl < OUTD) v = W2[(size_t)jl*K2TOT + kt + kk];
            Ws[kk][jl] = v;
        }
        __syncthreads();
        #pragma unroll
        for (int kk=0;kk<8;kk++){
            float a[8], wv[8];
            #pragma unroll
            for (int i=0;i<8;i++) a[i]  = As[kk][mi*8+i];
            #pragma unroll
            for (int j=0;j<8;j++) wv[j] = Ws[kk][ni*8+j];
            #pragma unroll
            for (int i=0;i<8;i++)
                #pragma unroll
                for (int j=0;j<8;j++) acc[i][j] += a[i]*wv[j];
        }
    }
    #pragma unroll
    for (int i=0;i<8;i++){
        int r2 = m0 + mi*8 + i;
        int tt = r2 >> 7, b = r2 & 127;
        size_t row = (size_t)(b*TT + tt)*OUTD;
        #pragma unroll
        for (int j=0;j<8;j++){
            int jg = ni*8 + j;
            if (jg < OUTD) out[row + jg] = acc[i][j] + b2[jg];
        }
    }
}

// ---------------- final states appended after out -----------------------------
__global__ void k_states(float* __restrict__ out, int out_size)
{
    const int base = BB*TT*OUTD;               // 3,964,928
    if (base + 4*BB*HH > out_size) return;     // guard if harness only wants `out`
    int i = blockIdx.x*256 + threadIdx.x;
    if (i < BB*HH){
        out[base            + i] = g_h1[i];
        out[base +   BB*HH  + i] = g_c1[i];
        out[base + 2*BB*HH  + i] = g_h2[i];
        out[base + 3*BB*HH  + i] = g_c2[i];
    }
}

// ---------------- launch -------------------------------------------------------
extern "C" void kernel_launch(void* const* d_in, const int* in_sizes, int n_in,
                              void* d_out, int out_size)
{
    const float* x    = (const float*)d_in[0];
    const float* sent = (const float*)d_in[1];
    const float* h1h  = (const float*)d_in[2];
    const float* h1c  = (const float*)d_in[3];
    const float* h2h  = (const float*)d_in[4];
    const float* h2c  = (const float*)d_in[5];
    const float* Wihc = (const float*)d_in[6];
    const float* Whhc = (const float*)d_in[7];
    const float* bc   = (const float*)d_in[8];
    const float* Wihl = (const float*)d_in[9];
    const float* Whhl = (const float*)d_in[10];
    const float* bl   = (const float*)d_in[11];
    const float* W1   = (const float*)d_in[12];
    const float* b1   = (const float*)d_in[13];
    const float* W2   = (const float*)d_in[14];
    const float* b2   = (const float*)d_in[15];
    float* out = (float*)d_out;

    k_init<<<256,256>>>(h1h,h1c,h2h,h2c);

    // layer 1: persistent attention + LSTMCell recurrence (1 launch, 256 steps)
    k_rec1<<<NBLK,256>>>(x, Wihc, Whhc, bc, W1, b1, sent);

    // layer 2 input gates for all t (time-parallel GEMM)
    k_l2in<<<dim3(16,TT),256>>>(x, Wihl, bl);

    // layer 2: persistent recurrence (1 launch, 256 steps)
    k_rec2<<<NBLK,256>>>(Whhl);

    // projection + final states
    k_out<<<256,256>>>(W2, b2, out);
    k_states<<<(BB*HH+255)/256,256>>>(out, out_size);
}